// round 9
// baseline (speedup 1.0000x reference)
#include <cuda_runtime.h>
#include <cstdint>

#define NB 16
#define TT 128
#define VV 64
#define FF 16
#define TBL 16                   // timesteps per k1 block
#define NTB (TT / TBL)           // 8 t-blocks
#define NK 32                    // k-offsets (pairs (i, i+k), k=1..32)
#define PADF 20                  // padded feature stride (80B, 16B-aligned)
#define K1_SMEM (TBL * VV * PADF * 4)   // 81920 B

// scratch[slice][n][k-1][i]  (8*16*32*64 floats = 1 MB)
__device__ __align__(16) float g_part[NTB * NB * NK * VV];

// Parity swizzle: even logical rows -> physical 0..31, odd -> 32..63.
__device__ __forceinline__ int prow(int r) {
    r &= 63;
    return (r >> 1) + ((r & 1) << 5);
}

// ---------------------------------------------------------------------------
// Kernel 1 (symmetric, 2-wide i blocking, single wave): for k=1..32,
//   partial[tb][n][k-1][i] = sum_{16 t, 16 f} a[f] * |x[t,i,f] - x[t,(i+k)%64,f]|
// 512 thr = 128 pair-threads x 4 t-slots (4 timesteps each). Thread owns
// i-rows {i0, i0+1} and k = k0+1..k0+8 (9 j-row loads serve 16 pairs).
// Grid 8x16 = 128 CTAs = ONE wave @ 1 CTA/SM (80KB smem, 64K regs).
// ---------------------------------------------------------------------------
__global__ __launch_bounds__(512, 1) void gl_partial_kernel(
    const float* __restrict__ x, const float* __restrict__ a)
{
    extern __shared__ __align__(16) float tile[];   // [TBL][VV][PADF] = 80 KB

    const int n   = blockIdx.y;
    const int tb  = blockIdx.x;
    const int tid = threadIdx.x;
    const int q    = tid & 127;       // pair-thread id
    const int slot = tid >> 7;        // t-slot 0..3
    const int i0   = (q & 31) * 2;    // even base vertex
    const int k0   = (q >> 5) * 8;    // k-group base (0,8,16,24)

    // Load tile: x[n, tb*16 : +16, :, :] contiguous (16384 floats).
    const float4* src = (const float4*)(x + (size_t)(n * TT + tb * TBL) * VV * FF);
#pragma unroll
    for (int w = tid; w < TBL * VV * 4; w += 512) {
        float4 v = src[w];
        int t  = w >> 8;              // 256 float4 per timestep
        int r  = w & 255;
        int vv = r >> 2;
        int f4 = r & 3;
        *(float4*)&tile[((size_t)t * VV + prow(vv)) * PADF + f4 * 4] = v;
    }

    // Pack a[f] pairs into f32x2 (low 32 bits = even f).
    uint64_t af2[8];
#pragma unroll
    for (int k = 0; k < 8; k++) {
        af2[k] = (uint64_t)__float_as_uint(__ldg(&a[2 * k])) |
                 ((uint64_t)__float_as_uint(__ldg(&a[2 * k + 1])) << 32);
    }
    __syncthreads();

    uint64_t acc[2][8];
#pragma unroll
    for (int m = 0; m < 2; m++)
#pragma unroll
        for (int d = 0; d < 8; d++) acc[m][d] = 0ull;

#pragma unroll 1
    for (int tt = 0; tt < 4; tt++) {
        const int t = slot * 4 + tt;
        // i-rows (phys: i0>>1 and i0>>1 + 32), negated for add2-based sub.
        uint64_t nzi[2][8];
#pragma unroll
        for (int m = 0; m < 2; m++) {
            const ulonglong2* zr = (const ulonglong2*)
                &tile[((size_t)t * VV + (i0 >> 1) + m * 32) * PADF];
            ulonglong2 z0 = zr[0], z1 = zr[1], z2 = zr[2], z3 = zr[3];
            nzi[m][0] = z0.x ^ 0x8000000080000000ULL;
            nzi[m][1] = z0.y ^ 0x8000000080000000ULL;
            nzi[m][2] = z1.x ^ 0x8000000080000000ULL;
            nzi[m][3] = z1.y ^ 0x8000000080000000ULL;
            nzi[m][4] = z2.x ^ 0x8000000080000000ULL;
            nzi[m][5] = z2.y ^ 0x8000000080000000ULL;
            nzi[m][6] = z3.x ^ 0x8000000080000000ULL;
            nzi[m][7] = z3.y ^ 0x8000000080000000ULL;
        }

#pragma unroll
        for (int r = 1; r <= 9; r++) {
            const ulonglong2* zjr = (const ulonglong2*)
                &tile[((size_t)t * VV + prow(i0 + k0 + r)) * PADF];
            ulonglong2 w0 = zjr[0], w1 = zjr[1], w2 = zjr[2], w3 = zjr[3];
            uint64_t zj[8] = {w0.x, w0.y, w1.x, w1.y, w2.x, w2.y, w3.x, w3.y};
            if (r <= 8) {             // pair (i0, i0+k0+r) -> acc[0][r-1]
#pragma unroll
                for (int p = 0; p < 8; p++) {
                    uint64_t d;
                    asm("add.rn.f32x2 %0, %1, %2;"
                        : "=l"(d) : "l"(nzi[0][p]), "l"(zj[p]));
                    d &= 0x7FFFFFFF7FFFFFFFULL;
                    asm("fma.rn.f32x2 %0, %1, %2, %3;"
                        : "=l"(acc[0][r - 1]) : "l"(af2[p]), "l"(d), "l"(acc[0][r - 1]));
                }
            }
            if (r >= 2) {             // pair (i0+1, i0+k0+r) -> acc[1][r-2]
#pragma unroll
                for (int p = 0; p < 8; p++) {
                    uint64_t d;
                    asm("add.rn.f32x2 %0, %1, %2;"
                        : "=l"(d) : "l"(nzi[1][p]), "l"(zj[p]));
                    d &= 0x7FFFFFFF7FFFFFFFULL;
                    asm("fma.rn.f32x2 %0, %1, %2, %3;"
                        : "=l"(acc[1][r - 2]) : "l"(af2[p]), "l"(d), "l"(acc[1][r - 2]));
                }
            }
        }
    }

    // Reduce packed halves to scalar per (m,d).
    float s[2][8];
#pragma unroll
    for (int m = 0; m < 2; m++)
#pragma unroll
        for (int d = 0; d < 8; d++)
            s[m][d] = __uint_as_float((unsigned)acc[m][d]) +
                      __uint_as_float((unsigned)(acc[m][d] >> 32));

    // Combine the 4 t-slots in (reused) smem: slots 1..3 write, slot 0 sums.
    __syncthreads();
    float* red = tile;                // 3 * 128 * 16 floats = 24 KB
    if (slot > 0) {
#pragma unroll
        for (int m = 0; m < 2; m++)
#pragma unroll
            for (int d = 0; d < 8; d++)
                red[(((slot - 1) * 128 + q) * 2 + m) * 8 + d] = s[m][d];
    }
    __syncthreads();
    if (slot == 0) {
        float* outp = &g_part[(((size_t)tb * NB + n) * NK + k0) * VV + i0];
#pragma unroll
        for (int d = 0; d < 8; d++) {
            float2 w;
            w.x = s[0][d] + red[(q * 2 + 0) * 8 + d]
                          + red[((128 + q) * 2 + 0) * 8 + d]
                          + red[((256 + q) * 2 + 0) * 8 + d];
            w.y = s[1][d] + red[(q * 2 + 1) * 8 + d]
                          + red[((128 + q) * 2 + 1) * 8 + d]
                          + red[((256 + q) * 2 + 1) * 8 + d];
            *(float2*)(outp + (size_t)d * VV) = w;    // [k-1][i0..i0+1]
        }
    }
}

// ---------------------------------------------------------------------------
// Kernel 2: one CTA per n (512 threads). 8 named slice loads (MLP-8, L2-hot
// 1MB scratch), e = exp(relu(mean)), symmetric scatter, column-normalize,
// store out[n,i,j].
// ---------------------------------------------------------------------------
__global__ __launch_bounds__(512) void gl_finalize_kernel(float* __restrict__ out)
{
    __shared__ float E[VV][VV + 2];
    __shared__ float cinv[VV];

    const int n   = blockIdx.x;
    const int tid = threadIdx.x;

    {   // Phase A: reduce 8 slices, independent named loads -> pairwise tree.
        const float4* g4 = (const float4*)g_part;
        const int base = n * (NK * VV / 4) + tid;     // n*512 + tid
        const int ss   = NB * NK * VV / 4;            // 8192 float4 / slice
        float4 v0 = g4[(size_t)0 * ss + base];
        float4 v1 = g4[(size_t)1 * ss + base];
        float4 v2 = g4[(size_t)2 * ss + base];
        float4 v3 = g4[(size_t)3 * ss + base];
        float4 v4 = g4[(size_t)4 * ss + base];
        float4 v5 = g4[(size_t)5 * ss + base];
        float4 v6 = g4[(size_t)6 * ss + base];
        float4 v7 = g4[(size_t)7 * ss + base];
        float4 s;
        s.x = ((v0.x + v1.x) + (v2.x + v3.x)) + ((v4.x + v5.x) + (v6.x + v7.x));
        s.y = ((v0.y + v1.y) + (v2.y + v3.y)) + ((v4.y + v5.y) + (v6.y + v7.y));
        s.z = ((v0.z + v1.z) + (v2.z + v3.z)) + ((v4.z + v5.z) + (v6.z + v7.z));
        s.w = ((v0.w + v1.w) + (v2.w + v3.w)) + ((v4.w + v5.w) + (v6.w + v7.w));

        const float inv = 1.0f / (float)TT;
        const int k_act = (tid >> 4) + 1;             // k (1..32)
        const int i0    = (tid & 15) * 4;
        float ev[4] = { expf(fmaxf(s.x * inv, 0.f)), expf(fmaxf(s.y * inv, 0.f)),
                        expf(fmaxf(s.z * inv, 0.f)), expf(fmaxf(s.w * inv, 0.f)) };
#pragma unroll
        for (int p = 0; p < 4; p++) {
            int ii = i0 + p;
            int jj = (ii + k_act) & 63;
            E[ii][jj] = ev[p];
            E[jj][ii] = ev[p];
        }
        if (tid < VV) E[tid][tid] = 1.0f;             // diag: exp(relu(0))
    }
    __syncthreads();

    {   // Phase B: column sums over i (16 warps x 4 columns).
        const int w = tid >> 5, lane = tid & 31;
#pragma unroll
        for (int c = 0; c < 4; c++) {
            int j = w * 4 + c;
            float v = E[lane][j] + E[lane + 32][j];
#pragma unroll
            for (int o = 16; o; o >>= 1) v += __shfl_xor_sync(0xffffffffu, v, o);
            if (lane == 0) cinv[j] = 1.0f / v;
        }
    }
    __syncthreads();

    {   // Phase C: out[n][i][j] = E[i][j] * cinv[j], 2x float4 stores.
        const int i  = tid >> 3;
        const int jb = (tid & 7) * 8;
        float4 w0, w1;
        w0.x = E[i][jb + 0] * cinv[jb + 0];
        w0.y = E[i][jb + 1] * cinv[jb + 1];
        w0.z = E[i][jb + 2] * cinv[jb + 2];
        w0.w = E[i][jb + 3] * cinv[jb + 3];
        w1.x = E[i][jb + 4] * cinv[jb + 4];
        w1.y = E[i][jb + 5] * cinv[jb + 5];
        w1.z = E[i][jb + 6] * cinv[jb + 6];
        w1.w = E[i][jb + 7] * cinv[jb + 7];
        float* o = out + (size_t)n * VV * VV + i * VV + jb;
        *(float4*)o       = w0;
        *(float4*)(o + 4) = w1;
    }
}

extern "C" void kernel_launch(void* const* d_in, const int* in_sizes, int n_in,
                              void* d_out, int out_size)
{
    const float* x = (const float*)d_in[0];       // [16,128,64,16] fp32
    const float* a = (const float*)d_in[1];       // [16,1] fp32
    float* out = (float*)d_out;                   // [16,64,64] fp32

    cudaFuncSetAttribute(gl_partial_kernel,
                         cudaFuncAttributeMaxDynamicSharedMemorySize, K1_SMEM);
    gl_partial_kernel<<<dim3(NTB, NB), 512, K1_SMEM>>>(x, a);
    gl_finalize_kernel<<<NB, 512>>>(out);
}

// round 10
// speedup vs baseline: 1.0363x; 1.0363x over previous
#include <cuda_runtime.h>
#include <cstdint>

#define NB 16
#define TT 128
#define VV 64
#define FF 16
#define TBL 16                   // timesteps per k1 block
#define NTB (TT / TBL)           // 8 t-blocks
#define NK 32                    // k-offsets (pairs (i, i+k), k=1..32)
#define PADF 20                  // padded feature stride (80B, 16B-aligned)
#define K1_SMEM (TBL * VV * PADF * 4)   // 81920 B

// scratch[slice][n][k-1][i]  (8*16*32*64 floats = 1 MB)
__device__ __align__(16) float g_part[NTB * NB * NK * VV];
// arrival counters per n (zero-init; finalizer resets -> graph-replay safe)
__device__ int g_cnt[NB];

// Parity swizzle: even logical rows -> physical 0..31, odd -> 32..63.
__device__ __forceinline__ int prow(int r) {
    r &= 63;
    return (r >> 1) + ((r & 1) << 5);
}

// ---------------------------------------------------------------------------
// Single fused kernel (symmetric, 2-wide i blocking, last-block finalize).
// Producer phase: partial[tb][n][k-1][i] = sum_{16 t,16 f} a[f]*|x_i - x_j|,
// j=(i+k)%64. 512 thr = 128 pair-threads x 4 t-slots. Grid 8x16 = 128 CTAs.
// The 8th CTA to finish a given n reduces the 8 slices (L2-hot), applies
// exp(relu(mean)), expands symmetric, column-normalizes, stores out[n,:,:].
// ---------------------------------------------------------------------------
__global__ __launch_bounds__(512, 1) void gl_fused_kernel(
    const float* __restrict__ x, const float* __restrict__ a,
    float* __restrict__ out)
{
    extern __shared__ __align__(16) float tile[];   // [TBL][VV][PADF] = 80 KB
    __shared__ int isLast;

    const int n   = blockIdx.y;
    const int tb  = blockIdx.x;
    const int tid = threadIdx.x;
    const int q    = tid & 127;       // pair-thread id
    const int slot = tid >> 7;        // t-slot 0..3
    const int i0   = (q & 31) * 2;    // even base vertex
    const int k0   = (q >> 5) * 8;    // k-group base (0,8,16,24)

    // Load tile: x[n, tb*16 : +16, :, :] contiguous (16384 floats).
    const float4* src = (const float4*)(x + (size_t)(n * TT + tb * TBL) * VV * FF);
#pragma unroll
    for (int w = tid; w < TBL * VV * 4; w += 512) {
        float4 v = src[w];
        int t  = w >> 8;              // 256 float4 per timestep
        int r  = w & 255;
        int vv = r >> 2;
        int f4 = r & 3;
        *(float4*)&tile[((size_t)t * VV + prow(vv)) * PADF + f4 * 4] = v;
    }

    // Pack a[f] pairs into f32x2 (low 32 bits = even f).
    uint64_t af2[8];
#pragma unroll
    for (int k = 0; k < 8; k++) {
        af2[k] = (uint64_t)__float_as_uint(__ldg(&a[2 * k])) |
                 ((uint64_t)__float_as_uint(__ldg(&a[2 * k + 1])) << 32);
    }
    __syncthreads();

    uint64_t acc[2][8];
#pragma unroll
    for (int m = 0; m < 2; m++)
#pragma unroll
        for (int d = 0; d < 8; d++) acc[m][d] = 0ull;

#pragma unroll 1
    for (int tt = 0; tt < 4; tt++) {
        const int t = slot * 4 + tt;
        // i-rows (phys: i0>>1 and i0>>1 + 32), negated for add2-based sub.
        uint64_t nzi[2][8];
#pragma unroll
        for (int m = 0; m < 2; m++) {
            const ulonglong2* zr = (const ulonglong2*)
                &tile[((size_t)t * VV + (i0 >> 1) + m * 32) * PADF];
            ulonglong2 z0 = zr[0], z1 = zr[1], z2 = zr[2], z3 = zr[3];
            nzi[m][0] = z0.x ^ 0x8000000080000000ULL;
            nzi[m][1] = z0.y ^ 0x8000000080000000ULL;
            nzi[m][2] = z1.x ^ 0x8000000080000000ULL;
            nzi[m][3] = z1.y ^ 0x8000000080000000ULL;
            nzi[m][4] = z2.x ^ 0x8000000080000000ULL;
            nzi[m][5] = z2.y ^ 0x8000000080000000ULL;
            nzi[m][6] = z3.x ^ 0x8000000080000000ULL;
            nzi[m][7] = z3.y ^ 0x8000000080000000ULL;
        }

#pragma unroll
        for (int r = 1; r <= 9; r++) {
            const ulonglong2* zjr = (const ulonglong2*)
                &tile[((size_t)t * VV + prow(i0 + k0 + r)) * PADF];
            ulonglong2 w0 = zjr[0], w1 = zjr[1], w2 = zjr[2], w3 = zjr[3];
            uint64_t zj[8] = {w0.x, w0.y, w1.x, w1.y, w2.x, w2.y, w3.x, w3.y};
            if (r <= 8) {             // pair (i0, i0+k0+r) -> acc[0][r-1]
#pragma unroll
                for (int p = 0; p < 8; p++) {
                    uint64_t d;
                    asm("add.rn.f32x2 %0, %1, %2;"
                        : "=l"(d) : "l"(nzi[0][p]), "l"(zj[p]));
                    d &= 0x7FFFFFFF7FFFFFFFULL;
                    asm("fma.rn.f32x2 %0, %1, %2, %3;"
                        : "=l"(acc[0][r - 1]) : "l"(af2[p]), "l"(d), "l"(acc[0][r - 1]));
                }
            }
            if (r >= 2) {             // pair (i0+1, i0+k0+r) -> acc[1][r-2]
#pragma unroll
                for (int p = 0; p < 8; p++) {
                    uint64_t d;
                    asm("add.rn.f32x2 %0, %1, %2;"
                        : "=l"(d) : "l"(nzi[1][p]), "l"(zj[p]));
                    d &= 0x7FFFFFFF7FFFFFFFULL;
                    asm("fma.rn.f32x2 %0, %1, %2, %3;"
                        : "=l"(acc[1][r - 2]) : "l"(af2[p]), "l"(d), "l"(acc[1][r - 2]));
                }
            }
        }
    }

    // Reduce packed halves to scalar per (m,d).
    float s[2][8];
#pragma unroll
    for (int m = 0; m < 2; m++)
#pragma unroll
        for (int d = 0; d < 8; d++)
            s[m][d] = __uint_as_float((unsigned)acc[m][d]) +
                      __uint_as_float((unsigned)(acc[m][d] >> 32));

    // Combine the 4 t-slots in (reused) smem: slots 1..3 write, slot 0 sums.
    __syncthreads();
    float* red = tile;                // 3 * 128 * 16 floats = 24 KB
    if (slot > 0) {
#pragma unroll
        for (int m = 0; m < 2; m++)
#pragma unroll
            for (int d = 0; d < 8; d++)
                red[(((slot - 1) * 128 + q) * 2 + m) * 8 + d] = s[m][d];
    }
    __syncthreads();
    if (slot == 0) {
        float* outp = &g_part[(((size_t)tb * NB + n) * NK + k0) * VV + i0];
#pragma unroll
        for (int d = 0; d < 8; d++) {
            float2 w;
            w.x = s[0][d] + red[(q * 2 + 0) * 8 + d]
                          + red[((128 + q) * 2 + 0) * 8 + d]
                          + red[((256 + q) * 2 + 0) * 8 + d];
            w.y = s[1][d] + red[(q * 2 + 1) * 8 + d]
                          + red[((128 + q) * 2 + 1) * 8 + d]
                          + red[((256 + q) * 2 + 1) * 8 + d];
            *(float2*)(outp + (size_t)d * VV) = w;    // [k-1][i0..i0+1]
        }
    }

    // ---- Last-block finalize for this n ----
    __threadfence();                  // partials visible before arrival
    __syncthreads();                  // all threads' stores issued
    if (tid == 0) {
        int old = atomicAdd(&g_cnt[n], 1);
        isLast = (old == NTB - 1);
    }
    __syncthreads();
    if (!isLast) return;

    // Reuse smem: E[64][66] + cinv[64]  (~17 KB of the 80 KB tile).
    float (*E)[VV + 2] = (float (*)[VV + 2])tile;
    float* cinv = tile + VV * (VV + 2);

    {   // Phase A: reduce 8 slices (L2-hot), e = exp(relu(mean)), scatter.
        const float4* g4 = (const float4*)g_part;
        const int base = n * (NK * VV / 4) + tid;     // n*512 + tid
        const int ss   = NB * NK * VV / 4;            // 8192 float4 / slice
        float4 v0 = g4[(size_t)0 * ss + base];
        float4 v1 = g4[(size_t)1 * ss + base];
        float4 v2 = g4[(size_t)2 * ss + base];
        float4 v3 = g4[(size_t)3 * ss + base];
        float4 v4 = g4[(size_t)4 * ss + base];
        float4 v5 = g4[(size_t)5 * ss + base];
        float4 v6 = g4[(size_t)6 * ss + base];
        float4 v7 = g4[(size_t)7 * ss + base];
        float4 sv;
        sv.x = ((v0.x + v1.x) + (v2.x + v3.x)) + ((v4.x + v5.x) + (v6.x + v7.x));
        sv.y = ((v0.y + v1.y) + (v2.y + v3.y)) + ((v4.y + v5.y) + (v6.y + v7.y));
        sv.z = ((v0.z + v1.z) + (v2.z + v3.z)) + ((v4.z + v5.z) + (v6.z + v7.z));
        sv.w = ((v0.w + v1.w) + (v2.w + v3.w)) + ((v4.w + v5.w) + (v6.w + v7.w));

        const float inv = 1.0f / (float)TT;
        const int k_act = (tid >> 4) + 1;             // k (1..32)
        const int ia    = (tid & 15) * 4;
        float ev[4] = { expf(fmaxf(sv.x * inv, 0.f)), expf(fmaxf(sv.y * inv, 0.f)),
                        expf(fmaxf(sv.z * inv, 0.f)), expf(fmaxf(sv.w * inv, 0.f)) };
#pragma unroll
        for (int p = 0; p < 4; p++) {
            int ii = ia + p;
            int jj = (ii + k_act) & 63;
            E[ii][jj] = ev[p];
            E[jj][ii] = ev[p];
        }
        if (tid < VV) E[tid][tid] = 1.0f;             // diag: exp(relu(0))
    }
    __syncthreads();

    {   // Phase B: column sums over i (16 warps x 4 columns).
        const int w = tid >> 5, lane = tid & 31;
#pragma unroll
        for (int c = 0; c < 4; c++) {
            int j = w * 4 + c;
            float v = E[lane][j] + E[lane + 32][j];
#pragma unroll
            for (int o = 16; o; o >>= 1) v += __shfl_xor_sync(0xffffffffu, v, o);
            if (lane == 0) cinv[j] = 1.0f / v;
        }
    }
    __syncthreads();

    {   // Phase C: out[n][i][j] = E[i][j] * cinv[j], 2x float4 stores.
        const int i  = tid >> 3;
        const int jb = (tid & 7) * 8;
        float4 w0, w1;
        w0.x = E[i][jb + 0] * cinv[jb + 0];
        w0.y = E[i][jb + 1] * cinv[jb + 1];
        w0.z = E[i][jb + 2] * cinv[jb + 2];
        w0.w = E[i][jb + 3] * cinv[jb + 3];
        w1.x = E[i][jb + 4] * cinv[jb + 4];
        w1.y = E[i][jb + 5] * cinv[jb + 5];
        w1.z = E[i][jb + 6] * cinv[jb + 6];
        w1.w = E[i][jb + 7] * cinv[jb + 7];
        float* o = out + (size_t)n * VV * VV + i * VV + jb;
        *(float4*)o       = w0;
        *(float4*)(o + 4) = w1;
    }

    if (tid == 0) g_cnt[n] = 0;       // reset for next graph replay
}

extern "C" void kernel_launch(void* const* d_in, const int* in_sizes, int n_in,
                              void* d_out, int out_size)
{
    const float* x = (const float*)d_in[0];       // [16,128,64,16] fp32
    const float* a = (const float*)d_in[1];       // [16,1] fp32
    float* out = (float*)d_out;                   // [16,64,64] fp32

    cudaFuncSetAttribute(gl_fused_kernel,
                         cudaFuncAttributeMaxDynamicSharedMemorySize, K1_SMEM);
    gl_fused_kernel<<<dim3(NTB, NB), 512, K1_SMEM>>>(x, a, out);
}